// round 4
// baseline (speedup 1.0000x reference)
#include <cuda_runtime.h>
#include <cuda_bf16.h>
#include <math_constants.h>
#include <cstdint>

// Attention B=256,H=16,Nq=Nk=49,D=64 fp32. One CTA (128 thr, 4 warps) per (b,h).
// bf16 hi/lo 3-term tensor-core GEMMs. Warp w owns q rows [16w,16w+16):
// S computed un-transposed; softmax in registers (quad shuffles); S C-fragments
// repacked in-register as A-fragments for P.V (no smem round trip for P).

namespace {
constexpr int kNQ = 49, kNK = 49, kD = 64;
constexpr int kP  = 72;                 // bf16 pitch (144B, odd multiple of 16B)
constexpr float kScale = 0.125f;
constexpr float kEps   = 1e-9f;
constexpr int OPELEMS = 64 * kP;        // 4608 bf16 per operand array
}

__device__ __forceinline__ uint32_t cvta_s(const void* p) {
    return (uint32_t)__cvta_generic_to_shared(p);
}
__device__ __forceinline__ void ldsm4(uint32_t& r0, uint32_t& r1, uint32_t& r2, uint32_t& r3, uint32_t a) {
    asm volatile("ldmatrix.sync.aligned.m8n8.x4.shared.b16 {%0,%1,%2,%3}, [%4];\n"
                 : "=r"(r0), "=r"(r1), "=r"(r2), "=r"(r3) : "r"(a));
}
__device__ __forceinline__ void ldsm4t(uint32_t& r0, uint32_t& r1, uint32_t& r2, uint32_t& r3, uint32_t a) {
    asm volatile("ldmatrix.sync.aligned.m8n8.x4.trans.shared.b16 {%0,%1,%2,%3}, [%4];\n"
                 : "=r"(r0), "=r"(r1), "=r"(r2), "=r"(r3) : "r"(a));
}
__device__ __forceinline__ void mma16816(float* c,
                                         uint32_t a0, uint32_t a1, uint32_t a2, uint32_t a3,
                                         uint32_t b0, uint32_t b1) {
    asm volatile("mma.sync.aligned.m16n8k16.row.col.f32.bf16.bf16.f32 "
                 "{%0,%1,%2,%3}, {%4,%5,%6,%7}, {%8,%9}, {%0,%1,%2,%3};\n"
                 : "+f"(c[0]), "+f"(c[1]), "+f"(c[2]), "+f"(c[3])
                 : "r"(a0), "r"(a1), "r"(a2), "r"(a3), "r"(b0), "r"(b1));
}
// pack two fp32 -> bf16x2 (lo = first arg, hi = second)
__device__ __forceinline__ uint32_t packbf2(float lo, float hi) {
    uint32_t r;
    asm("cvt.rn.bf16x2.f32 %0, %1, %2;" : "=r"(r) : "f"(hi), "f"(lo));
    return r;
}
__device__ __forceinline__ float2 unpackbf2(uint32_t h) {
    return make_float2(__uint_as_float(h << 16), __uint_as_float(h & 0xffff0000u));
}

__global__ __launch_bounds__(128)
void attn49_reg(const float* __restrict__ gq,
                const float* __restrict__ gk,
                const float* __restrict__ gv,
                float* __restrict__ gout)
{
    __shared__ __align__(16) __nv_bfloat16 sQh[OPELEMS];   // Q_hi -> V_hi
    __shared__ __align__(16) __nv_bfloat16 sQl[OPELEMS];   // Q_lo -> V_lo
    __shared__ __align__(16) __nv_bfloat16 sKh[OPELEMS];
    __shared__ __align__(16) __nv_bfloat16 sKl[OPELEMS];

    const int tid  = threadIdx.x;
    const int w    = tid >> 5;
    const int lane = tid & 31;
    const int g    = lane >> 3;
    const int lr   = lane & 7;

    const size_t base = (size_t)blockIdx.x * (kNQ * kD);
    const float2* Q2 = (const float2*)(gq + base);
    const float2* K2 = (const float2*)(gk + base);
    const float2* V2 = (const float2*)(gv + base);
    float* O = gout + base;

    uint32_t* Qh2 = (uint32_t*)sQh;
    uint32_t* Ql2 = (uint32_t*)sQl;
    uint32_t* Kh2 = (uint32_t*)sKh;
    uint32_t* Kl2 = (uint32_t*)sKl;

    // ---- Load + split Q (scaled) and K. Pad rows left garbage (masked later). ----
    for (int idx = tid; idx < (kNQ * kD) / 2; idx += 128) {
        const int r = idx >> 5, c2 = idx & 31;
        float2 q = Q2[idx];
        q.x *= kScale; q.y *= kScale;
        const float2 k = K2[idx];
        const uint32_t qh = packbf2(q.x, q.y);
        const float2  qf = unpackbf2(qh);
        const uint32_t kh = packbf2(k.x, k.y);
        const float2  kf = unpackbf2(kh);
        Qh2[r * 36 + c2] = qh;
        Ql2[r * 36 + c2] = packbf2(q.x - qf.x, q.y - qf.y);
        Kh2[r * 36 + c2] = kh;
        Kl2[r * 36 + c2] = packbf2(k.x - kf.x, k.y - kf.y);
    }
    __syncthreads();

    const int qtb = w * 16;

    // ---- Phase 1: S[q][k], acc[nt] covers n-cols [8nt, 8nt+8) ----
    float acc[8][4];
    #pragma unroll
    for (int i = 0; i < 8; i++)
        #pragma unroll
        for (int j = 0; j < 4; j++) acc[i][j] = 0.0f;
    {
        const uint32_t aQh = cvta_s(sQh), aQl = cvta_s(sQl);
        const uint32_t aKh = cvta_s(sKh), aKl = cvta_s(sKl);
        #pragma unroll
        for (int kc = 0; kc < 4; kc++) {
            const int d = kc * 16;
            const int ao = (qtb + lr + ((g & 1) << 3)) * kP + d + ((g >> 1) << 3);
            uint32_t ah0, ah1, ah2, ah3, al0, al1, al2, al3;
            ldsm4(ah0, ah1, ah2, ah3, aQh + ao * 2);
            ldsm4(al0, al1, al2, al3, aQl + ao * 2);
            #pragma unroll
            for (int nt2 = 0; nt2 < 4; nt2++) {
                const int bo = (nt2 * 16 + lr + ((g & 1) << 3)) * kP + d + ((g >> 1) << 3);
                uint32_t bh0, bh1, bh2, bh3, bl0, bl1, bl2, bl3;
                ldsm4(bh0, bh1, bh2, bh3, aKh + bo * 2);
                ldsm4(bl0, bl1, bl2, bl3, aKl + bo * 2);
                mma16816(acc[2 * nt2],     ah0, ah1, ah2, ah3, bh0, bh2);
                mma16816(acc[2 * nt2 + 1], ah0, ah1, ah2, ah3, bh1, bh3);
                mma16816(acc[2 * nt2],     ah0, ah1, ah2, ah3, bl0, bl2);
                mma16816(acc[2 * nt2 + 1], ah0, ah1, ah2, ah3, bl1, bl3);
                mma16816(acc[2 * nt2],     al0, al1, al2, al3, bh0, bh2);
                mma16816(acc[2 * nt2 + 1], al0, al1, al2, al3, bh1, bh3);
            }
        }
    }

    // ---- Softmax in registers. Row r0 = qtb + lane/4 (c0,c1), row r0+8 (c2,c3). ----
    const int cq = 2 * (lane & 3);
    float m0 = -CUDART_INF_F, m1 = -CUDART_INF_F;
    #pragma unroll
    for (int nt = 0; nt < 8; nt++) {
        const int c0 = nt * 8 + cq;
        const bool v0 = (c0 < kNK), v1 = (c0 + 1 < kNK);
        m0 = fmaxf(m0, v0 ? acc[nt][0] : -CUDART_INF_F);
        m0 = fmaxf(m0, v1 ? acc[nt][1] : -CUDART_INF_F);
        m1 = fmaxf(m1, v0 ? acc[nt][2] : -CUDART_INF_F);
        m1 = fmaxf(m1, v1 ? acc[nt][3] : -CUDART_INF_F);
    }
    m0 = fmaxf(m0, __shfl_xor_sync(0xffffffffu, m0, 1));
    m0 = fmaxf(m0, __shfl_xor_sync(0xffffffffu, m0, 2));
    m1 = fmaxf(m1, __shfl_xor_sync(0xffffffffu, m1, 1));
    m1 = fmaxf(m1, __shfl_xor_sync(0xffffffffu, m1, 2));

    float l0 = 0.0f, l1 = 0.0f;
    #pragma unroll
    for (int nt = 0; nt < 8; nt++) {
        const int c0 = nt * 8 + cq;
        const bool v0 = (c0 < kNK), v1 = (c0 + 1 < kNK);
        const float e0 = v0 ? __expf(acc[nt][0] - m0) : 0.0f;
        const float e1 = v1 ? __expf(acc[nt][1] - m0) : 0.0f;
        const float e2 = v0 ? __expf(acc[nt][2] - m1) : 0.0f;
        const float e3 = v1 ? __expf(acc[nt][3] - m1) : 0.0f;
        acc[nt][0] = e0; acc[nt][1] = e1; acc[nt][2] = e2; acc[nt][3] = e3;
        l0 += e0 + e1; l1 += e2 + e3;
    }
    l0 += __shfl_xor_sync(0xffffffffu, l0, 1);
    l0 += __shfl_xor_sync(0xffffffffu, l0, 2);
    l1 += __shfl_xor_sync(0xffffffffu, l1, 1);
    l1 += __shfl_xor_sync(0xffffffffu, l1, 2);
    const float linv0 = 1.0f / (l0 + kEps);
    const float linv1 = 1.0f / (l1 + kEps);

    // ---- Repack S C-fragments as A-fragments (m16k16) hi/lo, in registers ----
    uint32_t aH[4][4], aL[4][4];
    #pragma unroll
    for (int kc = 0; kc < 4; kc++) {
        #pragma unroll
        for (int t = 0; t < 2; t++) {           // n-tile 2kc+t
            const float e0 = acc[2 * kc + t][0], e1 = acc[2 * kc + t][1];
            const float e2 = acc[2 * kc + t][2], e3 = acc[2 * kc + t][3];
            const uint32_t h01 = packbf2(e0, e1);
            const uint32_t h23 = packbf2(e2, e3);
            const float2 f01 = unpackbf2(h01);
            const float2 f23 = unpackbf2(h23);
            aH[kc][2 * t]     = h01;
            aH[kc][2 * t + 1] = h23;
            aL[kc][2 * t]     = packbf2(e0 - f01.x, e1 - f01.y);
            aL[kc][2 * t + 1] = packbf2(e2 - f23.x, e3 - f23.y);
        }
    }

    // ---- V load + split into Q's (dead) buffers; zero pad rows 49..63 ----
    __syncthreads();
    for (int idx = tid; idx < (kNK * kD) / 2; idx += 128) {
        const int r = idx >> 5, c2 = idx & 31;
        const float2 v = V2[idx];
        const uint32_t vh = packbf2(v.x, v.y);
        const float2  vf = unpackbf2(vh);
        Qh2[r * 36 + c2] = vh;
        Ql2[r * 36 + c2] = packbf2(v.x - vf.x, v.y - vf.y);
    }
    for (int i = tid; i < 15 * 36; i += 128) {
        const int off = (kNK + i / 36) * 36 + (i % 36);
        Qh2[off] = 0u; Ql2[off] = 0u;
    }
    __syncthreads();

    // ---- Phase 2: O[16q][64d] = P.V, two d-halves of 32 ----
    const uint32_t aVh = cvta_s(sQh), aVl = cvta_s(sQl);
    const int q0 = qtb + (lane >> 2);
    const int q1 = q0 + 8;
    #pragma unroll
    for (int half = 0; half < 2; half++) {
        const int db = half * 32;
        float o[4][4];
        #pragma unroll
        for (int i = 0; i < 4; i++)
            #pragma unroll
            for (int j = 0; j < 4; j++) o[i][j] = 0.0f;

        #pragma unroll
        for (int kc = 0; kc < 4; kc++) {
            const int kk = kc * 16;
            #pragma unroll
            for (int nt2 = 0; nt2 < 2; nt2++) {
                const int bo = (kk + ((g >> 1) << 3) + lr) * kP + db + nt2 * 16 + ((g & 1) << 3);
                uint32_t bh0, bh1, bh2, bh3, bl0, bl1, bl2, bl3;
                ldsm4t(bh0, bh1, bh2, bh3, aVh + bo * 2);
                ldsm4t(bl0, bl1, bl2, bl3, aVl + bo * 2);
                mma16816(o[2 * nt2],     aH[kc][0], aH[kc][1], aH[kc][2], aH[kc][3], bh0, bh2);
                mma16816(o[2 * nt2 + 1], aH[kc][0], aH[kc][1], aH[kc][2], aH[kc][3], bh1, bh3);
                mma16816(o[2 * nt2],     aH[kc][0], aH[kc][1], aH[kc][2], aH[kc][3], bl0, bl2);
                mma16816(o[2 * nt2 + 1], aH[kc][0], aH[kc][1], aH[kc][2], aH[kc][3], bl1, bl3);
                mma16816(o[2 * nt2],     aL[kc][0], aL[kc][1], aL[kc][2], aL[kc][3], bh0, bh2);
                mma16816(o[2 * nt2 + 1], aL[kc][0], aL[kc][1], aL[kc][2], aL[kc][3], bh1, bh3);
            }
        }

        #pragma unroll
        for (int nt = 0; nt < 4; nt++) {
            const int d = db + nt * 8 + cq;
            if (q0 < kNQ)
                *(float2*)(O + q0 * kD + d) = make_float2(o[nt][0] * linv0, o[nt][1] * linv0);
            if (q1 < kNQ)
                *(float2*)(O + q1 * kD + d) = make_float2(o[nt][2] * linv1, o[nt][3] * linv1);
        }
    }
}

extern "C" void kernel_launch(void* const* d_in, const int* in_sizes, int n_in,
                              void* d_out, int out_size)
{
    const float* q = (const float*)d_in[0];
    const float* k = (const float*)d_in[1];
    const float* v = (const float*)d_in[2];
    float* out = (float*)d_out;

    const int bh = in_sizes[0] / (kNQ * kD);   // 4096
    attn49_reg<<<bh, 128>>>(q, k, v, out);
}

// round 5
// speedup vs baseline: 1.0701x; 1.0701x over previous
#include <cuda_runtime.h>
#include <cuda_bf16.h>
#include <math_constants.h>
#include <cstdint>

// Attention B=256,H=16,Nq=Nk=49,D=64 fp32. One CTA (128 thr, 4 warps) per (b,h).
// bf16 hi/lo 3-term tensor-core GEMMs. Warp w owns q rows [16w,16w+16).
// ALL inputs (Q,K,V) loaded+split upfront into dedicated smem buffers ->
// exactly ONE __syncthreads() in the whole kernel. Softmax + P repack fully
// in registers; phase-2 MMA starts immediately after softmax.

namespace {
constexpr int kNQ = 49, kNK = 49, kD = 64;
constexpr int kP  = 72;                 // bf16 pitch (144B, odd multiple of 16B)
constexpr float kScale = 0.125f;
constexpr float kEps   = 1e-9f;
constexpr int OPELEMS = 64 * kP;        // 4608 bf16 per operand array
constexpr int SMEM_BYTES = 6 * OPELEMS * 2;   // 55296
}

__device__ __forceinline__ uint32_t cvta_s(const void* p) {
    return (uint32_t)__cvta_generic_to_shared(p);
}
__device__ __forceinline__ void ldsm4(uint32_t& r0, uint32_t& r1, uint32_t& r2, uint32_t& r3, uint32_t a) {
    asm volatile("ldmatrix.sync.aligned.m8n8.x4.shared.b16 {%0,%1,%2,%3}, [%4];\n"
                 : "=r"(r0), "=r"(r1), "=r"(r2), "=r"(r3) : "r"(a));
}
__device__ __forceinline__ void ldsm4t(uint32_t& r0, uint32_t& r1, uint32_t& r2, uint32_t& r3, uint32_t a) {
    asm volatile("ldmatrix.sync.aligned.m8n8.x4.trans.shared.b16 {%0,%1,%2,%3}, [%4];\n"
                 : "=r"(r0), "=r"(r1), "=r"(r2), "=r"(r3) : "r"(a));
}
__device__ __forceinline__ void mma16816(float* c,
                                         uint32_t a0, uint32_t a1, uint32_t a2, uint32_t a3,
                                         uint32_t b0, uint32_t b1) {
    asm volatile("mma.sync.aligned.m16n8k16.row.col.f32.bf16.bf16.f32 "
                 "{%0,%1,%2,%3}, {%4,%5,%6,%7}, {%8,%9}, {%0,%1,%2,%3};\n"
                 : "+f"(c[0]), "+f"(c[1]), "+f"(c[2]), "+f"(c[3])
                 : "r"(a0), "r"(a1), "r"(a2), "r"(a3), "r"(b0), "r"(b1));
}
__device__ __forceinline__ uint32_t packbf2(float lo, float hi) {
    uint32_t r;
    asm("cvt.rn.bf16x2.f32 %0, %1, %2;" : "=r"(r) : "f"(hi), "f"(lo));
    return r;
}
__device__ __forceinline__ float2 unpackbf2(uint32_t h) {
    return make_float2(__uint_as_float(h << 16), __uint_as_float(h & 0xffff0000u));
}

__global__ __launch_bounds__(128)
void attn49_1bar(const float* __restrict__ gq,
                 const float* __restrict__ gk,
                 const float* __restrict__ gv,
                 float* __restrict__ gout)
{
    extern __shared__ __align__(16) char smem[];
    __nv_bfloat16* sQh = (__nv_bfloat16*)smem;
    __nv_bfloat16* sQl = sQh + OPELEMS;
    __nv_bfloat16* sKh = sQl + OPELEMS;
    __nv_bfloat16* sKl = sKh + OPELEMS;
    __nv_bfloat16* sVh = sKl + OPELEMS;
    __nv_bfloat16* sVl = sVh + OPELEMS;

    const int tid  = threadIdx.x;
    const int w    = tid >> 5;
    const int lane = tid & 31;
    const int g    = lane >> 3;
    const int lr   = lane & 7;

    const size_t base = (size_t)blockIdx.x * (kNQ * kD);
    const float2* Q2 = (const float2*)(gq + base);
    const float2* K2 = (const float2*)(gk + base);
    const float2* V2 = (const float2*)(gv + base);
    float* O = gout + base;

    uint32_t* Qh2 = (uint32_t*)sQh;
    uint32_t* Ql2 = (uint32_t*)sQl;
    uint32_t* Kh2 = (uint32_t*)sKh;
    uint32_t* Kl2 = (uint32_t*)sKl;
    uint32_t* Vh2 = (uint32_t*)sVh;
    uint32_t* Vl2 = (uint32_t*)sVl;

    // ---- Load + split Q (scaled), K, V upfront. Q/K pad rows stay garbage
    //      (masked downstream); V pad rows zeroed (P pad cols are exact 0). ----
    for (int idx = tid; idx < (kNQ * kD) / 2; idx += 128) {
        const int r = idx >> 5, c2 = idx & 31;
        float2 q = Q2[idx];
        const float2 k = K2[idx];
        const float2 v = V2[idx];
        q.x *= kScale; q.y *= kScale;
        const uint32_t qh = packbf2(q.x, q.y);
        const uint32_t kh = packbf2(k.x, k.y);
        const uint32_t vh = packbf2(v.x, v.y);
        const float2 qf = unpackbf2(qh);
        const float2 kf = unpackbf2(kh);
        const float2 vf = unpackbf2(vh);
        Qh2[r * 36 + c2] = qh;
        Ql2[r * 36 + c2] = packbf2(q.x - qf.x, q.y - qf.y);
        Kh2[r * 36 + c2] = kh;
        Kl2[r * 36 + c2] = packbf2(k.x - kf.x, k.y - kf.y);
        Vh2[r * 36 + c2] = vh;
        Vl2[r * 36 + c2] = packbf2(v.x - vf.x, v.y - vf.y);
    }
    for (int i = tid; i < 15 * 36; i += 128) {
        const int off = (kNK + i / 36) * 36 + (i % 36);
        Vh2[off] = 0u; Vl2[off] = 0u;
    }
    __syncthreads();   // the ONLY barrier

    const int qtb = w * 16;

    // ---- Phase 1: S[q][k] ----
    float acc[8][4];
    #pragma unroll
    for (int i = 0; i < 8; i++)
        #pragma unroll
        for (int j = 0; j < 4; j++) acc[i][j] = 0.0f;
    {
        const uint32_t aQh = cvta_s(sQh), aQl = cvta_s(sQl);
        const uint32_t aKh = cvta_s(sKh), aKl = cvta_s(sKl);
        #pragma unroll
        for (int kc = 0; kc < 4; kc++) {
            const int d = kc * 16;
            const int ao = (qtb + lr + ((g & 1) << 3)) * kP + d + ((g >> 1) << 3);
            uint32_t ah0, ah1, ah2, ah3, al0, al1, al2, al3;
            ldsm4(ah0, ah1, ah2, ah3, aQh + ao * 2);
            ldsm4(al0, al1, al2, al3, aQl + ao * 2);
            #pragma unroll
            for (int nt2 = 0; nt2 < 4; nt2++) {
                const int bo = (nt2 * 16 + lr + ((g & 1) << 3)) * kP + d + ((g >> 1) << 3);
                uint32_t bh0, bh1, bh2, bh3, bl0, bl1, bl2, bl3;
                ldsm4(bh0, bh1, bh2, bh3, aKh + bo * 2);
                ldsm4(bl0, bl1, bl2, bl3, aKl + bo * 2);
                mma16816(acc[2 * nt2],     ah0, ah1, ah2, ah3, bh0, bh2);
                mma16816(acc[2 * nt2 + 1], ah0, ah1, ah2, ah3, bh1, bh3);
                mma16816(acc[2 * nt2],     ah0, ah1, ah2, ah3, bl0, bl2);
                mma16816(acc[2 * nt2 + 1], ah0, ah1, ah2, ah3, bl1, bl3);
                mma16816(acc[2 * nt2],     al0, al1, al2, al3, bh0, bh2);
                mma16816(acc[2 * nt2 + 1], al0, al1, al2, al3, bh1, bh3);
            }
        }
    }

    // ---- Register softmax: row r0 = qtb + lane/4 (acc[..][0,1]); row r0+8 (acc[..][2,3]) ----
    const int cq = 2 * (lane & 3);
    float m0 = -CUDART_INF_F, m1 = -CUDART_INF_F;
    #pragma unroll
    for (int nt = 0; nt < 8; nt++) {
        const int c0 = nt * 8 + cq;
        const bool v0 = (c0 < kNK), v1 = (c0 + 1 < kNK);
        m0 = fmaxf(m0, v0 ? acc[nt][0] : -CUDART_INF_F);
        m0 = fmaxf(m0, v1 ? acc[nt][1] : -CUDART_INF_F);
        m1 = fmaxf(m1, v0 ? acc[nt][2] : -CUDART_INF_F);
        m1 = fmaxf(m1, v1 ? acc[nt][3] : -CUDART_INF_F);
    }
    m0 = fmaxf(m0, __shfl_xor_sync(0xffffffffu, m0, 1));
    m0 = fmaxf(m0, __shfl_xor_sync(0xffffffffu, m0, 2));
    m1 = fmaxf(m1, __shfl_xor_sync(0xffffffffu, m1, 1));
    m1 = fmaxf(m1, __shfl_xor_sync(0xffffffffu, m1, 2));

    float l0 = 0.0f, l1 = 0.0f;
    #pragma unroll
    for (int nt = 0; nt < 8; nt++) {
        const int c0 = nt * 8 + cq;
        const bool v0 = (c0 < kNK), v1 = (c0 + 1 < kNK);
        const float e0 = v0 ? __expf(acc[nt][0] - m0) : 0.0f;
        const float e1 = v1 ? __expf(acc[nt][1] - m0) : 0.0f;
        const float e2 = v0 ? __expf(acc[nt][2] - m1) : 0.0f;
        const float e3 = v1 ? __expf(acc[nt][3] - m1) : 0.0f;
        acc[nt][0] = e0; acc[nt][1] = e1; acc[nt][2] = e2; acc[nt][3] = e3;
        l0 += e0 + e1; l1 += e2 + e3;
    }
    l0 += __shfl_xor_sync(0xffffffffu, l0, 1);
    l0 += __shfl_xor_sync(0xffffffffu, l0, 2);
    l1 += __shfl_xor_sync(0xffffffffu, l1, 1);
    l1 += __shfl_xor_sync(0xffffffffu, l1, 2);
    const float linv0 = 1.0f / (l0 + kEps);
    const float linv1 = 1.0f / (l1 + kEps);

    // ---- Repack S C-fragments as A-fragments (m16k16) hi/lo, in registers ----
    uint32_t aH[4][4], aL[4][4];
    #pragma unroll
    for (int kc = 0; kc < 4; kc++) {
        #pragma unroll
        for (int t = 0; t < 2; t++) {
            const float e0 = acc[2 * kc + t][0], e1 = acc[2 * kc + t][1];
            const float e2 = acc[2 * kc + t][2], e3 = acc[2 * kc + t][3];
            const uint32_t h01 = packbf2(e0, e1);
            const uint32_t h23 = packbf2(e2, e3);
            const float2 f01 = unpackbf2(h01);
            const float2 f23 = unpackbf2(h23);
            aH[kc][2 * t]     = h01;
            aH[kc][2 * t + 1] = h23;
            aL[kc][2 * t]     = packbf2(e0 - f01.x, e1 - f01.y);
            aL[kc][2 * t + 1] = packbf2(e2 - f23.x, e3 - f23.y);
        }
    }

    // ---- Phase 2: O = P.V (V already resident since barrier) ----
    const uint32_t aVh = cvta_s(sVh), aVl = cvta_s(sVl);
    const int q0 = qtb + (lane >> 2);
    const int q1 = q0 + 8;
    #pragma unroll
    for (int half = 0; half < 2; half++) {
        const int db = half * 32;
        float o[4][4];
        #pragma unroll
        for (int i = 0; i < 4; i++)
            #pragma unroll
            for (int j = 0; j < 4; j++) o[i][j] = 0.0f;

        #pragma unroll
        for (int kc = 0; kc < 4; kc++) {
            const int kk = kc * 16;
            #pragma unroll
            for (int nt2 = 0; nt2 < 2; nt2++) {
                const int bo = (kk + ((g >> 1) << 3) + lr) * kP + db + nt2 * 16 + ((g & 1) << 3);
                uint32_t bh0, bh1, bh2, bh3, bl0, bl1, bl2, bl3;
                ldsm4t(bh0, bh1, bh2, bh3, aVh + bo * 2);
                ldsm4t(bl0, bl1, bl2, bl3, aVl + bo * 2);
                mma16816(o[2 * nt2],     aH[kc][0], aH[kc][1], aH[kc][2], aH[kc][3], bh0, bh2);
                mma16816(o[2 * nt2 + 1], aH[kc][0], aH[kc][1], aH[kc][2], aH[kc][3], bh1, bh3);
                mma16816(o[2 * nt2],     aH[kc][0], aH[kc][1], aH[kc][2], aH[kc][3], bl0, bl2);
                mma16816(o[2 * nt2 + 1], aH[kc][0], aH[kc][1], aH[kc][2], aH[kc][3], bl1, bl3);
                mma16816(o[2 * nt2],     aL[kc][0], aL[kc][1], aL[kc][2], aL[kc][3], bh0, bh2);
                mma16816(o[2 * nt2 + 1], aL[kc][0], aL[kc][1], aL[kc][2], aL[kc][3], bh1, bh3);
            }
        }

        #pragma unroll
        for (int nt = 0; nt < 4; nt++) {
            const int d = db + nt * 8 + cq;
            if (q0 < kNQ)
                *(float2*)(O + q0 * kD + d) = make_float2(o[nt][0] * linv0, o[nt][1] * linv0);
            if (q1 < kNQ)
                *(float2*)(O + q1 * kD + d) = make_float2(o[nt][2] * linv1, o[nt][3] * linv1);
        }
    }
}

extern "C" void kernel_launch(void* const* d_in, const int* in_sizes, int n_in,
                              void* d_out, int out_size)
{
    const float* q = (const float*)d_in[0];
    const float* k = (const float*)d_in[1];
    const float* v = (const float*)d_in[2];
    float* out = (float*)d_out;

    static bool attr_set = false;
    if (!attr_set) {
        cudaFuncSetAttribute(attn49_1bar, cudaFuncAttributeMaxDynamicSharedMemorySize, SMEM_BYTES);
        attr_set = true;
    }
    const int bh = in_sizes[0] / (kNQ * kD);   // 4096
    attn49_1bar<<<bh, 128, SMEM_BYTES>>>(q, k, v, out);
}

// round 6
// speedup vs baseline: 1.2103x; 1.1310x over previous
#include <cuda_runtime.h>
#include <cuda_bf16.h>
#include <math_constants.h>
#include <cstdint>

// Attention B=256,H=16,Nq=Nk=49,D=64 fp32. One CTA (128 thr, 4 warps) per (b,h).
// bf16 hi/lo 3-term tensor-core GEMMs. Warp w owns q rows [16w,16w+16).
// Q loaded DIRECTLY from gmem into A-fragments (registers) - no Q smem.
// Only K,V hi/lo in smem (36.9KB) -> 6 CTAs/SM. One __syncthreads().
// Softmax + P repack fully in registers.

namespace {
constexpr int kNQ = 49, kNK = 49, kD = 64;
constexpr int kP  = 72;                 // bf16 pitch (144B, odd multiple of 16B)
constexpr float kScale = 0.125f;
constexpr float kEps   = 1e-9f;
constexpr int OPELEMS = 64 * kP;        // 4608 bf16 per operand array
}

__device__ __forceinline__ uint32_t cvta_s(const void* p) {
    return (uint32_t)__cvta_generic_to_shared(p);
}
__device__ __forceinline__ void ldsm4(uint32_t& r0, uint32_t& r1, uint32_t& r2, uint32_t& r3, uint32_t a) {
    asm volatile("ldmatrix.sync.aligned.m8n8.x4.shared.b16 {%0,%1,%2,%3}, [%4];\n"
                 : "=r"(r0), "=r"(r1), "=r"(r2), "=r"(r3) : "r"(a));
}
__device__ __forceinline__ void ldsm4t(uint32_t& r0, uint32_t& r1, uint32_t& r2, uint32_t& r3, uint32_t a) {
    asm volatile("ldmatrix.sync.aligned.m8n8.x4.trans.shared.b16 {%0,%1,%2,%3}, [%4];\n"
                 : "=r"(r0), "=r"(r1), "=r"(r2), "=r"(r3) : "r"(a));
}
__device__ __forceinline__ void mma16816(float* c,
                                         uint32_t a0, uint32_t a1, uint32_t a2, uint32_t a3,
                                         uint32_t b0, uint32_t b1) {
    asm volatile("mma.sync.aligned.m16n8k16.row.col.f32.bf16.bf16.f32 "
                 "{%0,%1,%2,%3}, {%4,%5,%6,%7}, {%8,%9}, {%0,%1,%2,%3};\n"
                 : "+f"(c[0]), "+f"(c[1]), "+f"(c[2]), "+f"(c[3])
                 : "r"(a0), "r"(a1), "r"(a2), "r"(a3), "r"(b0), "r"(b1));
}
__device__ __forceinline__ uint32_t packbf2(float lo, float hi) {
    uint32_t r;
    asm("cvt.rn.bf16x2.f32 %0, %1, %2;" : "=r"(r) : "f"(hi), "f"(lo));
    return r;
}
__device__ __forceinline__ float2 unpackbf2(uint32_t h) {
    return make_float2(__uint_as_float(h << 16), __uint_as_float(h & 0xffff0000u));
}

__global__ __launch_bounds__(128, 6)
void attn49_qreg(const float* __restrict__ gq,
                 const float* __restrict__ gk,
                 const float* __restrict__ gv,
                 float* __restrict__ gout)
{
    __shared__ __align__(16) __nv_bfloat16 sKh[OPELEMS];
    __shared__ __align__(16) __nv_bfloat16 sKl[OPELEMS];
    __shared__ __align__(16) __nv_bfloat16 sVh[OPELEMS];
    __shared__ __align__(16) __nv_bfloat16 sVl[OPELEMS];

    const int tid  = threadIdx.x;
    const int w    = tid >> 5;
    const int lane = tid & 31;
    const int g    = lane >> 3;
    const int lr   = lane & 7;

    const size_t base = (size_t)blockIdx.x * (kNQ * kD);
    const float2* Q2 = (const float2*)(gq + base);
    const float2* K2 = (const float2*)(gk + base);
    const float2* V2 = (const float2*)(gv + base);
    float* O = gout + base;

    const int qtb = w * 16;
    const int q0 = qtb + (lane >> 2);
    const int q1 = q0 + 8;
    const bool p0 = q0 < kNQ;
    const bool p1 = q1 < kNQ;
    const int cq = 2 * (lane & 3);

    // ---- Q A-fragments straight from gmem (scale + hi/lo split in regs) ----
    uint32_t qAh[4][4], qAl[4][4];
    #pragma unroll
    for (int kc = 0; kc < 4; kc++) {
        const int cb = kc * 8 + (lane & 3);            // float2 units within row
        float2 x0 = p0 ? Q2[q0 * 32 + cb]     : make_float2(0.f, 0.f);
        float2 x1 = p1 ? Q2[q1 * 32 + cb]     : make_float2(0.f, 0.f);
        float2 x2 = p0 ? Q2[q0 * 32 + cb + 4] : make_float2(0.f, 0.f);
        float2 x3 = p1 ? Q2[q1 * 32 + cb + 4] : make_float2(0.f, 0.f);
        x0.x *= kScale; x0.y *= kScale; x1.x *= kScale; x1.y *= kScale;
        x2.x *= kScale; x2.y *= kScale; x3.x *= kScale; x3.y *= kScale;
        const uint32_t h0 = packbf2(x0.x, x0.y);
        const uint32_t h1 = packbf2(x1.x, x1.y);
        const uint32_t h2 = packbf2(x2.x, x2.y);
        const uint32_t h3 = packbf2(x3.x, x3.y);
        const float2 f0 = unpackbf2(h0), f1 = unpackbf2(h1);
        const float2 f2 = unpackbf2(h2), f3 = unpackbf2(h3);
        qAh[kc][0] = h0; qAh[kc][1] = h1; qAh[kc][2] = h2; qAh[kc][3] = h3;
        qAl[kc][0] = packbf2(x0.x - f0.x, x0.y - f0.y);
        qAl[kc][1] = packbf2(x1.x - f1.x, x1.y - f1.y);
        qAl[kc][2] = packbf2(x2.x - f2.x, x2.y - f2.y);
        qAl[kc][3] = packbf2(x3.x - f3.x, x3.y - f3.y);
    }

    // ---- Cooperative K,V load + split into smem ----
    uint32_t* Kh2 = (uint32_t*)sKh;
    uint32_t* Kl2 = (uint32_t*)sKl;
    uint32_t* Vh2 = (uint32_t*)sVh;
    uint32_t* Vl2 = (uint32_t*)sVl;
    for (int idx = tid; idx < (kNK * kD) / 2; idx += 128) {
        const int r = idx >> 5, c2 = idx & 31;
        const float2 k = K2[idx];
        const float2 v = V2[idx];
        const uint32_t kh = packbf2(k.x, k.y);
        const uint32_t vh = packbf2(v.x, v.y);
        const float2 kf = unpackbf2(kh);
        const float2 vf = unpackbf2(vh);
        Kh2[r * 36 + c2] = kh;
        Kl2[r * 36 + c2] = packbf2(k.x - kf.x, k.y - kf.y);
        Vh2[r * 36 + c2] = vh;
        Vl2[r * 36 + c2] = packbf2(v.x - vf.x, v.y - vf.y);
    }
    // V pad rows must be finite (P pad cols are exact zeros); K pads are masked.
    for (int i = tid; i < 15 * 36; i += 128) {
        const int off = (kNK + i / 36) * 36 + (i % 36);
        Vh2[off] = 0u; Vl2[off] = 0u;
    }
    __syncthreads();   // the ONLY barrier

    // ---- Phase 1: S[q][k] ----
    float acc[8][4];
    #pragma unroll
    for (int i = 0; i < 8; i++)
        #pragma unroll
        for (int j = 0; j < 4; j++) acc[i][j] = 0.0f;
    {
        const uint32_t aKh = cvta_s(sKh), aKl = cvta_s(sKl);
        #pragma unroll
        for (int kc = 0; kc < 4; kc++) {
            const int d = kc * 16;
            #pragma unroll
            for (int nt2 = 0; nt2 < 4; nt2++) {
                const int bo = (nt2 * 16 + lr + ((g & 1) << 3)) * kP + d + ((g >> 1) << 3);
                uint32_t bh0, bh1, bh2, bh3, bl0, bl1, bl2, bl3;
                ldsm4(bh0, bh1, bh2, bh3, aKh + bo * 2);
                ldsm4(bl0, bl1, bl2, bl3, aKl + bo * 2);
                mma16816(acc[2 * nt2],     qAh[kc][0], qAh[kc][1], qAh[kc][2], qAh[kc][3], bh0, bh2);
                mma16816(acc[2 * nt2 + 1], qAh[kc][0], qAh[kc][1], qAh[kc][2], qAh[kc][3], bh1, bh3);
                mma16816(acc[2 * nt2],     qAh[kc][0], qAh[kc][1], qAh[kc][2], qAh[kc][3], bl0, bl2);
                mma16816(acc[2 * nt2 + 1], qAh[kc][0], qAh[kc][1], qAh[kc][2], qAh[kc][3], bl1, bl3);
                mma16816(acc[2 * nt2],     qAl[kc][0], qAl[kc][1], qAl[kc][2], qAl[kc][3], bh0, bh2);
                mma16816(acc[2 * nt2 + 1], qAl[kc][0], qAl[kc][1], qAl[kc][2], qAl[kc][3], bh1, bh3);
            }
        }
    }

    // ---- Register softmax (rows q0: acc[..][0,1]; q1: acc[..][2,3]) ----
    float m0 = -CUDART_INF_F, m1 = -CUDART_INF_F;
    #pragma unroll
    for (int nt = 0; nt < 8; nt++) {
        const int c0 = nt * 8 + cq;
        const bool v0 = (c0 < kNK), v1 = (c0 + 1 < kNK);
        m0 = fmaxf(m0, v0 ? acc[nt][0] : -CUDART_INF_F);
        m0 = fmaxf(m0, v1 ? acc[nt][1] : -CUDART_INF_F);
        m1 = fmaxf(m1, v0 ? acc[nt][2] : -CUDART_INF_F);
        m1 = fmaxf(m1, v1 ? acc[nt][3] : -CUDART_INF_F);
    }
    m0 = fmaxf(m0, __shfl_xor_sync(0xffffffffu, m0, 1));
    m0 = fmaxf(m0, __shfl_xor_sync(0xffffffffu, m0, 2));
    m1 = fmaxf(m1, __shfl_xor_sync(0xffffffffu, m1, 1));
    m1 = fmaxf(m1, __shfl_xor_sync(0xffffffffu, m1, 2));

    float l0 = 0.0f, l1 = 0.0f;
    #pragma unroll
    for (int nt = 0; nt < 8; nt++) {
        const int c0 = nt * 8 + cq;
        const bool v0 = (c0 < kNK), v1 = (c0 + 1 < kNK);
        const float e0 = v0 ? __expf(acc[nt][0] - m0) : 0.0f;
        const float e1 = v1 ? __expf(acc[nt][1] - m0) : 0.0f;
        const float e2 = v0 ? __expf(acc[nt][2] - m1) : 0.0f;
        const float e3 = v1 ? __expf(acc[nt][3] - m1) : 0.0f;
        acc[nt][0] = e0; acc[nt][1] = e1; acc[nt][2] = e2; acc[nt][3] = e3;
        l0 += e0 + e1; l1 += e2 + e3;
    }
    l0 += __shfl_xor_sync(0xffffffffu, l0, 1);
    l0 += __shfl_xor_sync(0xffffffffu, l0, 2);
    l1 += __shfl_xor_sync(0xffffffffu, l1, 1);
    l1 += __shfl_xor_sync(0xffffffffu, l1, 2);
    const float linv0 = 1.0f / (l0 + kEps);
    const float linv1 = 1.0f / (l1 + kEps);

    // ---- Repack S C-fragments as A-fragments (m16k16) hi/lo, in registers ----
    uint32_t aH[4][4], aL[4][4];
    #pragma unroll
    for (int kc = 0; kc < 4; kc++) {
        #pragma unroll
        for (int t = 0; t < 2; t++) {
            const float e0 = acc[2 * kc + t][0], e1 = acc[2 * kc + t][1];
            const float e2 = acc[2 * kc + t][2], e3 = acc[2 * kc + t][3];
            const uint32_t h01 = packbf2(e0, e1);
            const uint32_t h23 = packbf2(e2, e3);
            const float2 f01 = unpackbf2(h01);
            const float2 f23 = unpackbf2(h23);
            aH[kc][2 * t]     = h01;
            aH[kc][2 * t + 1] = h23;
            aL[kc][2 * t]     = packbf2(e0 - f01.x, e1 - f01.y);
            aL[kc][2 * t + 1] = packbf2(e2 - f23.x, e3 - f23.y);
        }
    }

    // ---- Phase 2: O = P.V ----
    const uint32_t aVh = cvta_s(sVh), aVl = cvta_s(sVl);
    #pragma unroll
    for (int half = 0; half < 2; half++) {
        const int db = half * 32;
        float o[4][4];
        #pragma unroll
        for (int i = 0; i < 4; i++)
            #pragma unroll
            for (int j = 0; j < 4; j++) o[i][j] = 0.0f;

        #pragma unroll
        for (int kc = 0; kc < 4; kc++) {
            const int kk = kc * 16;
            #pragma unroll
            for (int nt2 = 0; nt2 < 2; nt2++) {
                const int bo = (kk + ((g >> 1) << 3) + lr) * kP + db + nt2 * 16 + ((g & 1) << 3);
                uint32_t bh0, bh1, bh2, bh3, bl0, bl1, bl2, bl3;
                ldsm4t(bh0, bh1, bh2, bh3, aVh + bo * 2);
                ldsm4t(bl0, bl1, bl2, bl3, aVl + bo * 2);
                mma16816(o[2 * nt2],     aH[kc][0], aH[kc][1], aH[kc][2], aH[kc][3], bh0, bh2);
                mma16816(o[2 * nt2 + 1], aH[kc][0], aH[kc][1], aH[kc][2], aH[kc][3], bh1, bh3);
                mma16816(o[2 * nt2],     aH[kc][0], aH[kc][1], aH[kc][2], aH[kc][3], bl0, bl2);
                mma16816(o[2 * nt2 + 1], aH[kc][0], aH[kc][1], aH[kc][2], aH[kc][3], bl1, bl3);
                mma16816(o[2 * nt2],     aL[kc][0], aL[kc][1], aL[kc][2], aL[kc][3], bh0, bh2);
                mma16816(o[2 * nt2 + 1], aL[kc][0], aL[kc][1], aL[kc][2], aL[kc][3], bh1, bh3);
            }
        }

        #pragma unroll
        for (int nt = 0; nt < 4; nt++) {
            const int d = db + nt * 8 + cq;
            if (p0)
                *(float2*)(O + q0 * kD + d) = make_float2(o[nt][0] * linv0, o[nt][1] * linv0);
            if (p1)
                *(float2*)(O + q1 * kD + d) = make_float2(o[nt][2] * linv1, o[nt][3] * linv1);
        }
    }
}

extern "C" void kernel_launch(void* const* d_in, const int* in_sizes, int n_in,
                              void* d_out, int out_size)
{
    const float* q = (const float*)d_in[0];
    const float* k = (const float*)d_in[1];
    const float* v = (const float*)d_in[2];
    float* out = (float*)d_out;

    const int bh = in_sizes[0] / (kNQ * kD);   // 4096
    attn49_qreg<<<bh, 128>>>(q, k, v, out);
}